// round 5
// baseline (speedup 1.0000x reference)
#include <cuda_runtime.h>

#define T_STEPS 64
#define N_NODES 20000
#define NW      592    // 148 blocks x 4 warps = 1 warp per SMSP
#define NB5     33     // blocks 0..32 run V=5 (132 warps x 40 nodes); rest V=4

__device__ float g_scratch[T_STEPS * NW];

typedef unsigned long long ull;

__device__ __forceinline__ ull pack2(float v) {
    ull r; asm("mov.b64 %0, {%1, %1};" : "=l"(r) : "f"(v)); return r;
}
__device__ __forceinline__ void fma2(ull &acc, ull a, ull b) {
    asm("fma.rn.f32x2 %0, %1, %2, %0;" : "+l"(acc) : "l"(a), "l"(b));
}
__device__ __forceinline__ void unpack2(ull v, float &a, float &b) {
    asm("mov.b64 {%0, %1}, %2;" : "=f"(a), "=f"(b) : "l"(v));
}
__device__ __forceinline__ float sigm(float v) { return __fdividef(1.0f, 1.0f + __expf(-v)); }
__device__ __forceinline__ float tanhf_(float v) { return fmaf(2.0f, sigm(2.0f * v), -1.0f); }
__device__ __forceinline__ float lrelu(float v) { return fmaxf(v, 0.01f * v); }

struct SW {
    float z[40 * 32];   // rows 0..7 = Wx*, 8..39 = Wh*
    float r[40 * 32];
    float h[40 * 32];
    float cbz[32], cbr[32], cbh[32], w1[32];
};

template<int V>
__device__ __forceinline__ void gru_warp(
    const SW* __restrict__ sw, const float* __restrict__ x,
    const float* __restrict__ h0, const float* __restrict__ W2,
    float b1s, float* __restrict__ out, int out_size, int base, int gw)
{
    const int lane = threadIdx.x & 31;
    const int s  = lane & 3;       // slice: owns h-cols j0..j0+7
    const int g8 = lane >> 2;      // group 0..7
    const int gb = lane & 28;
    const int j0 = s * 8;

    int   node[V];
    float hreg[V][8], w2r[V];

#pragma unroll
    for (int u = 0; u < V; u++) {
        node[u] = base + u * 8 + g8;
#pragma unroll
        for (int i = 0; i < 8; i++) hreg[u][i] = h0[node[u] * 32 + j0 + i];
        w2r[u] = W2[node[u]];
    }
    float w1r[8];
#pragma unroll
    for (int i = 0; i < 8; i++) w1r[i] = sw->w1[j0 + i];

    ull bz[4], br[4], bh[4];
#pragma unroll
    for (int i = 0; i < 4; i++) {
        bz[i] = ((const ull*)&sw->cbz[j0])[i];
        br[i] = ((const ull*)&sw->cbr[j0])[i];
        bh[i] = ((const ull*)&sw->cbh[j0])[i];
    }

#pragma unroll 1
    for (int t = 0; t < T_STEPS; ++t) {
        ull az[V][4], ar[V][4], ah[V][4];
#pragma unroll
        for (int u = 0; u < V; u++)
#pragma unroll
            for (int i = 0; i < 4; i++) {
                az[u][i] = bz[i]; ar[u][i] = br[i]; ah[u][i] = bh[i];
            }

        // ---------- x-part for all three gates, half of x at a time ----------
        const float* xb = x + (size_t)t * (N_NODES * 8);
        {
            float4 xa[V];
#pragma unroll
            for (int u = 0; u < V; u++)
                xa[u] = *(const float4*)(xb + (size_t)node[u] * 8);
#pragma unroll
            for (int c = 0; c < 4; c++) {
                const ulonglong2 wz0 = *(const ulonglong2*)&sw->z[c * 32 + j0];
                const ulonglong2 wz1 = *(const ulonglong2*)&sw->z[c * 32 + j0 + 4];
                const ulonglong2 wr0 = *(const ulonglong2*)&sw->r[c * 32 + j0];
                const ulonglong2 wr1 = *(const ulonglong2*)&sw->r[c * 32 + j0 + 4];
                const ulonglong2 wh0 = *(const ulonglong2*)&sw->h[c * 32 + j0];
                const ulonglong2 wh1 = *(const ulonglong2*)&sw->h[c * 32 + j0 + 4];
#pragma unroll
                for (int u = 0; u < V; u++) {
                    float xv = (c == 0) ? xa[u].x : (c == 1) ? xa[u].y : (c == 2) ? xa[u].z : xa[u].w;
                    ull m = pack2(xv);
                    fma2(az[u][0], m, wz0.x); fma2(az[u][1], m, wz0.y);
                    fma2(az[u][2], m, wz1.x); fma2(az[u][3], m, wz1.y);
                    fma2(ar[u][0], m, wr0.x); fma2(ar[u][1], m, wr0.y);
                    fma2(ar[u][2], m, wr1.x); fma2(ar[u][3], m, wr1.y);
                    fma2(ah[u][0], m, wh0.x); fma2(ah[u][1], m, wh0.y);
                    fma2(ah[u][2], m, wh1.x); fma2(ah[u][3], m, wh1.y);
                }
            }
        }
        {
            float4 xa[V];
#pragma unroll
            for (int u = 0; u < V; u++)
                xa[u] = *(const float4*)(xb + (size_t)node[u] * 8 + 4);
#pragma unroll
            for (int c = 0; c < 4; c++) {
                const int k = 4 + c;
                const ulonglong2 wz0 = *(const ulonglong2*)&sw->z[k * 32 + j0];
                const ulonglong2 wz1 = *(const ulonglong2*)&sw->z[k * 32 + j0 + 4];
                const ulonglong2 wr0 = *(const ulonglong2*)&sw->r[k * 32 + j0];
                const ulonglong2 wr1 = *(const ulonglong2*)&sw->r[k * 32 + j0 + 4];
                const ulonglong2 wh0 = *(const ulonglong2*)&sw->h[k * 32 + j0];
                const ulonglong2 wh1 = *(const ulonglong2*)&sw->h[k * 32 + j0 + 4];
#pragma unroll
                for (int u = 0; u < V; u++) {
                    float xv = (c == 0) ? xa[u].x : (c == 1) ? xa[u].y : (c == 2) ? xa[u].z : xa[u].w;
                    ull m = pack2(xv);
                    fma2(az[u][0], m, wz0.x); fma2(az[u][1], m, wz0.y);
                    fma2(az[u][2], m, wz1.x); fma2(az[u][3], m, wz1.y);
                    fma2(ar[u][0], m, wr0.x); fma2(ar[u][1], m, wr0.y);
                    fma2(ar[u][2], m, wr1.x); fma2(ar[u][3], m, wr1.y);
                    fma2(ah[u][0], m, wh0.x); fma2(ah[u][1], m, wh0.y);
                    fma2(ah[u][2], m, wh1.x); fma2(ah[u][3], m, wh1.y);
                }
            }
        }

        // ---------- phase 1 h-part: az, ar += Wh{z,r} . h ----------
#pragma unroll 1
        for (int sp = 0; sp < 4; sp++) {
#pragma unroll
            for (int c = 0; c < 8; c++) {
                const int k = 8 + sp * 8 + c;
                const ulonglong2 wz0 = *(const ulonglong2*)&sw->z[k * 32 + j0];
                const ulonglong2 wz1 = *(const ulonglong2*)&sw->z[k * 32 + j0 + 4];
                const ulonglong2 wr0 = *(const ulonglong2*)&sw->r[k * 32 + j0];
                const ulonglong2 wr1 = *(const ulonglong2*)&sw->r[k * 32 + j0 + 4];
#pragma unroll
                for (int u = 0; u < V; u++) {
                    ull m = pack2(__shfl_sync(0xffffffffu, hreg[u][c], gb + sp));
                    fma2(az[u][0], m, wz0.x); fma2(az[u][1], m, wz0.y);
                    fma2(az[u][2], m, wz1.x); fma2(az[u][3], m, wz1.y);
                    fma2(ar[u][0], m, wr0.x); fma2(ar[u][1], m, wr0.y);
                    fma2(ar[u][2], m, wr1.x); fma2(ar[u][3], m, wr1.y);
                }
            }
        }

        // ---------- gates (az/ar die here; zz/gg born) ----------
        float zz[V][8], gg[V][8];
#pragma unroll
        for (int u = 0; u < V; u++)
#pragma unroll
            for (int i = 0; i < 4; i++) {
                float a, b;
                unpack2(az[u][i], a, b);
                zz[u][2*i] = sigm(a); zz[u][2*i+1] = sigm(b);
                unpack2(ar[u][i], a, b);
                gg[u][2*i]   = hreg[u][2*i]   * sigm(a);
                gg[u][2*i+1] = hreg[u][2*i+1] * sigm(b);
            }

        // ---------- phase 2 h-part: ah += Whh . (h*r) ----------
#pragma unroll 1
        for (int sp = 0; sp < 4; sp++) {
#pragma unroll
            for (int c = 0; c < 8; c++) {
                const int k = 8 + sp * 8 + c;
                const ulonglong2 w0 = *(const ulonglong2*)&sw->h[k * 32 + j0];
                const ulonglong2 w1 = *(const ulonglong2*)&sw->h[k * 32 + j0 + 4];
#pragma unroll
                for (int u = 0; u < V; u++) {
                    ull m = pack2(__shfl_sync(0xffffffffu, gg[u][c], gb + sp));
                    fma2(ah[u][0], m, w0.x); fma2(ah[u][1], m, w0.y);
                    fma2(ah[u][2], m, w1.x); fma2(ah[u][3], m, w1.y);
                }
            }
        }

        // ---------- update + fused readout ----------
        float st = 0.0f;
#pragma unroll
        for (int u = 0; u < V; u++) {
            float p = 0.0f;
#pragma unroll
            for (int i = 0; i < 4; i++) {
                float a, b;
                unpack2(ah[u][i], a, b);
                float t0 = tanhf_(a), t1 = tanhf_(b);
                float h0v = hreg[u][2*i], h1v = hreg[u][2*i+1];
                float hn0 = t0 + zz[u][2*i]   * (h0v - t0);
                float hn1 = t1 + zz[u][2*i+1] * (h1v - t1);
                hreg[u][2*i] = hn0; hreg[u][2*i+1] = hn1;
                p = fmaf(lrelu(hn0), w1r[2*i],   p);
                p = fmaf(lrelu(hn1), w1r[2*i+1], p);
            }
            p += __shfl_xor_sync(0xffffffffu, p, 1);
            p += __shfl_xor_sync(0xffffffffu, p, 2);
            st += lrelu(p + b1s) * w2r[u];
        }
        st += __shfl_xor_sync(0xffffffffu, st, 4);
        st += __shfl_xor_sync(0xffffffffu, st, 8);
        st += __shfl_xor_sync(0xffffffffu, st, 16);
        if (lane == 0) g_scratch[t * NW + gw] = st;
    }

    if (out_size >= N_NODES * 32) {
        const int hoff = out_size - N_NODES * 32;
#pragma unroll
        for (int u = 0; u < V; u++)
#pragma unroll
            for (int i = 0; i < 8; i++)
                out[hoff + node[u] * 32 + j0 + i] = hreg[u][i];
    }
}

__global__ void __launch_bounds__(128, 1)
gru_kernel(const float* __restrict__ x, const float* __restrict__ h0,
           const float* __restrict__ Wxz, const float* __restrict__ bxz,
           const float* __restrict__ Whz, const float* __restrict__ bhz,
           const float* __restrict__ Wxr, const float* __restrict__ bxr,
           const float* __restrict__ Whr, const float* __restrict__ bhr,
           const float* __restrict__ Wxh, const float* __restrict__ bxh,
           const float* __restrict__ Whh, const float* __restrict__ bhh,
           const float* __restrict__ W1,  const float* __restrict__ b1,
           const float* __restrict__ W2,
           float* __restrict__ out, int out_size)
{
    __shared__ __align__(16) SW sw;

    for (int i = threadIdx.x; i < 8 * 32; i += 128) {
        sw.z[i] = Wxz[i]; sw.r[i] = Wxr[i]; sw.h[i] = Wxh[i];
    }
    for (int i = threadIdx.x; i < 32 * 32; i += 128) {
        sw.z[256 + i] = Whz[i]; sw.r[256 + i] = Whr[i]; sw.h[256 + i] = Whh[i];
    }
    if (threadIdx.x < 32) {
        int i = threadIdx.x;
        sw.cbz[i] = bxz[i] + bhz[i];
        sw.cbr[i] = bxr[i] + bhr[i];
        sw.cbh[i] = bxh[i] + bhh[i];
        sw.w1[i]  = W1[i];
    }
    __syncthreads();

    const int gw = blockIdx.x * 4 + (threadIdx.x >> 5);
    const float b1s = b1[0];

    if (blockIdx.x < NB5) {
        gru_warp<5>(&sw, x, h0, W2, b1s, out, out_size, 40 * gw, gw);
    } else {
        gru_warp<4>(&sw, x, h0, W2, b1s, out, out_size,
                    5280 + 32 * (gw - 4 * NB5), gw);
    }
}

__global__ void reduce_out(const float* __restrict__ b2,
                           float* __restrict__ out, int out_size)
{
    const int t = blockIdx.x;
    float s = 0.0f;
    for (int w = threadIdx.x; w < NW; w += 256)
        s += g_scratch[t * NW + w];
#pragma unroll
    for (int o = 16; o; o >>= 1) s += __shfl_xor_sync(0xffffffffu, s, o);
    __shared__ float red[8];
    if ((threadIdx.x & 31) == 0) red[threadIdx.x >> 5] = s;
    __syncthreads();
    if (threadIdx.x < 8) {
        s = red[threadIdx.x];
#pragma unroll
        for (int o = 4; o; o >>= 1) s += __shfl_xor_sync(0x000000ffu, s, o);
        if (threadIdx.x == 0) {
            bool wr = (out_size >= T_STEPS + N_NODES * 32) || (out_size < N_NODES * 32);
            if (wr && t < out_size) out[t] = s + b2[0];
        }
    }
}

extern "C" void kernel_launch(void* const* d_in, const int* in_sizes, int n_in,
                              void* d_out, int out_size) {
    const float* x   = (const float*)d_in[0];
    const float* h0  = (const float*)d_in[3];
    const float* Wxz = (const float*)d_in[4];
    const float* bxz = (const float*)d_in[5];
    const float* Whz = (const float*)d_in[6];
    const float* bhz = (const float*)d_in[7];
    const float* Wxr = (const float*)d_in[8];
    const float* bxr = (const float*)d_in[9];
    const float* Whr = (const float*)d_in[10];
    const float* bhr = (const float*)d_in[11];
    const float* Wxh = (const float*)d_in[12];
    const float* bxh = (const float*)d_in[13];
    const float* Whh = (const float*)d_in[14];
    const float* bhh = (const float*)d_in[15];
    const float* W1  = (const float*)d_in[16];
    const float* b1  = (const float*)d_in[17];
    const float* W2  = (const float*)d_in[18];
    const float* b2  = (const float*)d_in[19];
    float* out = (float*)d_out;

    gru_kernel<<<148, 128>>>(x, h0, Wxz, bxz, Whz, bhz, Wxr, bxr, Whr, bhr,
                             Wxh, bxh, Whh, bhh, W1, b1, W2, out, out_size);
    reduce_out<<<T_STEPS, 256>>>(b2, out, out_size);
}

// round 6
// speedup vs baseline: 3.0321x; 3.0321x over previous
#include <cuda_runtime.h>

#define T_STEPS 64
#define N_NODES 20000
#define NW      592    // 148 blocks x 4 warps = 1 warp per SMSP
#define NB5     33     // blocks 0..32 run V=5 (132 warps x 40 nodes); rest V=4

__device__ float g_scratch[T_STEPS * NW];

typedef unsigned long long ull;

__device__ __forceinline__ ull pack2(float v) {
    ull r; asm("mov.b64 %0, {%1, %1};" : "=l"(r) : "f"(v)); return r;
}
__device__ __forceinline__ void fma2(ull &acc, ull a, ull b) {
    asm("fma.rn.f32x2 %0, %1, %2, %0;" : "+l"(acc) : "l"(a), "l"(b));
}
__device__ __forceinline__ void unpack2(ull v, float &a, float &b) {
    asm("mov.b64 {%0, %1}, %2;" : "=f"(a), "=f"(b) : "l"(v));
}
__device__ __forceinline__ float tanha(float v) {
    float r; asm("tanh.approx.f32 %0, %1;" : "=f"(r) : "f"(v)); return r;
}
__device__ __forceinline__ float sigm(float v) {
    return fmaf(0.5f, tanha(0.5f * v), 0.5f);
}
__device__ __forceinline__ float lrelu(float v) { return fmaxf(v, 0.01f * v); }

struct SW {
    float z[40 * 32];   // rows 0..7 = Wx*, 8..39 = Wh*
    float r[40 * 32];
    float h[40 * 32];
    float cbz[32], cbr[32], cbh[32], w1[32];
};

template<int V>
__device__ __forceinline__ void gru_warp(
    const SW* __restrict__ sw, const float* __restrict__ x,
    const float* __restrict__ h0, const float* __restrict__ W2,
    float b1s, float* __restrict__ out, int out_size, int base, int gw)
{
    const int lane = threadIdx.x & 31;
    const int s  = lane & 3;       // slice: owns h-cols j0..j0+7
    const int g8 = lane >> 2;      // group 0..7
    const int gb = lane & 28;
    const int j0 = s * 8;

    int   node[V];
    float hreg[V][8], w2r[V];

#pragma unroll
    for (int u = 0; u < V; u++) {
        node[u] = base + u * 8 + g8;
#pragma unroll
        for (int i = 0; i < 8; i++) hreg[u][i] = h0[node[u] * 32 + j0 + i];
        w2r[u] = W2[node[u]];
    }
    float w1r[8];
#pragma unroll
    for (int i = 0; i < 8; i++) w1r[i] = sw->w1[j0 + i];

    ull bz[4], br[4], bh[4];
#pragma unroll
    for (int i = 0; i < 4; i++) {
        bz[i] = ((const ull*)&sw->cbz[j0])[i];
        br[i] = ((const ull*)&sw->cbr[j0])[i];
        bh[i] = ((const ull*)&sw->cbh[j0])[i];
    }

#pragma unroll 1
    for (int t = 0; t < T_STEPS; ++t) {
        // x for this step
        float x8[V][8];
        {
            const float* xb = x + (size_t)t * (N_NODES * 8);
#pragma unroll
            for (int u = 0; u < V; u++) {
                float4 a = *(const float4*)(xb + (size_t)node[u] * 8);
                float4 b = *(const float4*)(xb + (size_t)node[u] * 8 + 4);
                x8[u][0]=a.x; x8[u][1]=a.y; x8[u][2]=a.z; x8[u][3]=a.w;
                x8[u][4]=b.x; x8[u][5]=b.y; x8[u][6]=b.z; x8[u][7]=b.w;
            }
        }

        // ---------- phase 1: z, r pre-activations ----------
        ull az[V][4], ar[V][4];
#pragma unroll
        for (int u = 0; u < V; u++)
#pragma unroll
            for (int i = 0; i < 4; i++) { az[u][i] = bz[i]; ar[u][i] = br[i]; }

        // h-part: sp rolled, c unrolled
#pragma unroll 1
        for (int sp = 0; sp < 4; sp++) {
#pragma unroll
            for (int c = 0; c < 8; c++) {
                const int k = 8 + sp * 8 + c;
                const ulonglong2 wz0 = *(const ulonglong2*)&sw->z[k * 32 + j0];
                const ulonglong2 wz1 = *(const ulonglong2*)&sw->z[k * 32 + j0 + 4];
                const ulonglong2 wr0 = *(const ulonglong2*)&sw->r[k * 32 + j0];
                const ulonglong2 wr1 = *(const ulonglong2*)&sw->r[k * 32 + j0 + 4];
#pragma unroll
                for (int u = 0; u < V; u++) {
                    ull m = pack2(__shfl_sync(0xffffffffu, hreg[u][c], gb + sp));
                    fma2(az[u][0], m, wz0.x); fma2(az[u][1], m, wz0.y);
                    fma2(az[u][2], m, wz1.x); fma2(az[u][3], m, wz1.y);
                    fma2(ar[u][0], m, wr0.x); fma2(ar[u][1], m, wr0.y);
                    fma2(ar[u][2], m, wr1.x); fma2(ar[u][3], m, wr1.y);
                }
            }
        }
        // x-part
#pragma unroll
        for (int c = 0; c < 8; c++) {
            const ulonglong2 wz0 = *(const ulonglong2*)&sw->z[c * 32 + j0];
            const ulonglong2 wz1 = *(const ulonglong2*)&sw->z[c * 32 + j0 + 4];
            const ulonglong2 wr0 = *(const ulonglong2*)&sw->r[c * 32 + j0];
            const ulonglong2 wr1 = *(const ulonglong2*)&sw->r[c * 32 + j0 + 4];
#pragma unroll
            for (int u = 0; u < V; u++) {
                ull m = pack2(x8[u][c]);
                fma2(az[u][0], m, wz0.x); fma2(az[u][1], m, wz0.y);
                fma2(az[u][2], m, wz1.x); fma2(az[u][3], m, wz1.y);
                fma2(ar[u][0], m, wr0.x); fma2(ar[u][1], m, wr0.y);
                fma2(ar[u][2], m, wr1.x); fma2(ar[u][3], m, wr1.y);
            }
        }

        // ---------- gg = h * sigmoid(r)  (ar dies here) ----------
        float gg[V][8];
#pragma unroll
        for (int u = 0; u < V; u++)
#pragma unroll
            for (int i = 0; i < 4; i++) {
                float a, b;
                unpack2(ar[u][i], a, b);
                gg[u][2*i]   = hreg[u][2*i]   * sigm(a);
                gg[u][2*i+1] = hreg[u][2*i+1] * sigm(b);
            }

        // ---------- phase 2: candidate ----------
        ull ah[V][4];
#pragma unroll
        for (int u = 0; u < V; u++)
#pragma unroll
            for (int i = 0; i < 4; i++) ah[u][i] = bh[i];

        // x-part first (x8 dies here)
#pragma unroll
        for (int c = 0; c < 8; c++) {
            const ulonglong2 w0 = *(const ulonglong2*)&sw->h[c * 32 + j0];
            const ulonglong2 w1 = *(const ulonglong2*)&sw->h[c * 32 + j0 + 4];
#pragma unroll
            for (int u = 0; u < V; u++) {
                ull m = pack2(x8[u][c]);
                fma2(ah[u][0], m, w0.x); fma2(ah[u][1], m, w0.y);
                fma2(ah[u][2], m, w1.x); fma2(ah[u][3], m, w1.y);
            }
        }

        // ---------- zz = sigmoid(az) (az dies; independent of p2h below) ----------
        float zz[V][8];
#pragma unroll
        for (int u = 0; u < V; u++)
#pragma unroll
            for (int i = 0; i < 4; i++) {
                float a, b;
                unpack2(az[u][i], a, b);
                zz[u][2*i] = sigm(a); zz[u][2*i+1] = sigm(b);
            }

        // p2 h-part: ah += Whh . (h*r)
#pragma unroll 1
        for (int sp = 0; sp < 4; sp++) {
#pragma unroll
            for (int c = 0; c < 8; c++) {
                const int k = 8 + sp * 8 + c;
                const ulonglong2 w0 = *(const ulonglong2*)&sw->h[k * 32 + j0];
                const ulonglong2 w1 = *(const ulonglong2*)&sw->h[k * 32 + j0 + 4];
#pragma unroll
                for (int u = 0; u < V; u++) {
                    ull m = pack2(__shfl_sync(0xffffffffu, gg[u][c], gb + sp));
                    fma2(ah[u][0], m, w0.x); fma2(ah[u][1], m, w0.y);
                    fma2(ah[u][2], m, w1.x); fma2(ah[u][3], m, w1.y);
                }
            }
        }

        // ---------- update + fused readout ----------
        float st = 0.0f;
#pragma unroll
        for (int u = 0; u < V; u++) {
            float p = 0.0f;
#pragma unroll
            for (int i = 0; i < 4; i++) {
                float a, b;
                unpack2(ah[u][i], a, b);
                float t0 = tanha(a), t1 = tanha(b);
                float h0v = hreg[u][2*i], h1v = hreg[u][2*i+1];
                float hn0 = t0 + zz[u][2*i]   * (h0v - t0);
                float hn1 = t1 + zz[u][2*i+1] * (h1v - t1);
                hreg[u][2*i] = hn0; hreg[u][2*i+1] = hn1;
                p = fmaf(lrelu(hn0), w1r[2*i],   p);
                p = fmaf(lrelu(hn1), w1r[2*i+1], p);
            }
            p += __shfl_xor_sync(0xffffffffu, p, 1);
            p += __shfl_xor_sync(0xffffffffu, p, 2);
            st += lrelu(p + b1s) * w2r[u];
        }
        st += __shfl_xor_sync(0xffffffffu, st, 4);
        st += __shfl_xor_sync(0xffffffffu, st, 8);
        st += __shfl_xor_sync(0xffffffffu, st, 16);
        if (lane == 0) g_scratch[t * NW + gw] = st;
    }

    if (out_size >= N_NODES * 32) {
        const int hoff = out_size - N_NODES * 32;
#pragma unroll
        for (int u = 0; u < V; u++)
#pragma unroll
            for (int i = 0; i < 8; i++)
                out[hoff + node[u] * 32 + j0 + i] = hreg[u][i];
    }
}

__global__ void __launch_bounds__(128, 1)
gru_kernel(const float* __restrict__ x, const float* __restrict__ h0,
           const float* __restrict__ Wxz, const float* __restrict__ bxz,
           const float* __restrict__ Whz, const float* __restrict__ bhz,
           const float* __restrict__ Wxr, const float* __restrict__ bxr,
           const float* __restrict__ Whr, const float* __restrict__ bhr,
           const float* __restrict__ Wxh, const float* __restrict__ bxh,
           const float* __restrict__ Whh, const float* __restrict__ bhh,
           const float* __restrict__ W1,  const float* __restrict__ b1,
           const float* __restrict__ W2,
           float* __restrict__ out, int out_size)
{
    __shared__ __align__(16) SW sw;

    for (int i = threadIdx.x; i < 8 * 32; i += 128) {
        sw.z[i] = Wxz[i]; sw.r[i] = Wxr[i]; sw.h[i] = Wxh[i];
    }
    for (int i = threadIdx.x; i < 32 * 32; i += 128) {
        sw.z[256 + i] = Whz[i]; sw.r[256 + i] = Whr[i]; sw.h[256 + i] = Whh[i];
    }
    if (threadIdx.x < 32) {
        int i = threadIdx.x;
        sw.cbz[i] = bxz[i] + bhz[i];
        sw.cbr[i] = bxr[i] + bhr[i];
        sw.cbh[i] = bxh[i] + bhh[i];
        sw.w1[i]  = W1[i];
    }
    __syncthreads();

    const int gw = blockIdx.x * 4 + (threadIdx.x >> 5);
    const float b1s = b1[0];

    if (blockIdx.x < NB5) {
        gru_warp<5>(&sw, x, h0, W2, b1s, out, out_size, 40 * gw, gw);
    } else {
        gru_warp<4>(&sw, x, h0, W2, b1s, out, out_size,
                    5280 + 32 * (gw - 4 * NB5), gw);
    }
}

__global__ void reduce_out(const float* __restrict__ b2,
                           float* __restrict__ out, int out_size)
{
    const int t = blockIdx.x;
    float s = 0.0f;
    for (int w = threadIdx.x; w < NW; w += 256)
        s += g_scratch[t * NW + w];
#pragma unroll
    for (int o = 16; o; o >>= 1) s += __shfl_xor_sync(0xffffffffu, s, o);
    __shared__ float red[8];
    if ((threadIdx.x & 31) == 0) red[threadIdx.x >> 5] = s;
    __syncthreads();
    if (threadIdx.x < 8) {
        s = red[threadIdx.x];
#pragma unroll
        for (int o = 4; o; o >>= 1) s += __shfl_xor_sync(0x000000ffu, s, o);
        if (threadIdx.x == 0) {
            bool wr = (out_size >= T_STEPS + N_NODES * 32) || (out_size < N_NODES * 32);
            if (wr && t < out_size) out[t] = s + b2[0];
        }
    }
}

extern "C" void kernel_launch(void* const* d_in, const int* in_sizes, int n_in,
                              void* d_out, int out_size) {
    const float* x   = (const float*)d_in[0];
    const float* h0  = (const float*)d_in[3];
    const float* Wxz = (const float*)d_in[4];
    const float* bxz = (const float*)d_in[5];
    const float* Whz = (const float*)d_in[6];
    const float* bhz = (const float*)d_in[7];
    const float* Wxr = (const float*)d_in[8];
    const float* bxr = (const float*)d_in[9];
    const float* Whr = (const float*)d_in[10];
    const float* bhr = (const float*)d_in[11];
    const float* Wxh = (const float*)d_in[12];
    const float* bxh = (const float*)d_in[13];
    const float* Whh = (const float*)d_in[14];
    const float* bhh = (const float*)d_in[15];
    const float* W1  = (const float*)d_in[16];
    const float* b1  = (const float*)d_in[17];
    const float* W2  = (const float*)d_in[18];
    const float* b2  = (const float*)d_in[19];
    float* out = (float*)d_out;

    gru_kernel<<<148, 128>>>(x, h0, Wxz, bxz, Whz, bhz, Wxr, bxr, Whr, bhr,
                             Wxh, bxh, Whh, bhh, W1, b1, W2, out, out_size);
    reduce_out<<<T_STEPS, 256>>>(b2, out, out_size);
}

// round 7
// speedup vs baseline: 3.0668x; 1.0115x over previous
#include <cuda_runtime.h>

#define T_STEPS 64
#define N_NODES 20000
#define NW      592    // 148 blocks x 4 warps = 1 warp per SMSP
#define NB5     33     // blocks 0..32 run V=5 (132 warps x 40 nodes); rest V=4

__device__ float g_scratch[T_STEPS * NW];

typedef unsigned long long ull;

__device__ __forceinline__ ull pack2(float v) {
    ull r; asm("mov.b64 %0, {%1, %1};" : "=l"(r) : "f"(v)); return r;
}
__device__ __forceinline__ void fma2(ull &acc, ull a, ull b) {
    asm("fma.rn.f32x2 %0, %1, %2, %0;" : "+l"(acc) : "l"(a), "l"(b));
}
__device__ __forceinline__ void unpack2(ull v, float &a, float &b) {
    asm("mov.b64 {%0, %1}, %2;" : "=f"(a), "=f"(b) : "l"(v));
}
__device__ __forceinline__ float tanha(float v) {
    float r; asm("tanh.approx.f32 %0, %1;" : "=f"(r) : "f"(v)); return r;
}
__device__ __forceinline__ float sigm(float v) {
    return fmaf(0.5f, tanha(0.5f * v), 0.5f);
}
__device__ __forceinline__ float lrelu(float v) { return fmaxf(v, 0.01f * v); }

struct SW {
    float z[40 * 32];   // rows 0..7 = Wx*, 8..39 = Wh*
    float r[40 * 32];
    float h[40 * 32];
    float cbz[32], cbr[32], cbh[32], w1[32];
};

template<int V>
__device__ __forceinline__ void gru_warp(
    const SW* __restrict__ sw, const float* __restrict__ x,
    const float* __restrict__ h0, const float* __restrict__ W2,
    float b1s, float* __restrict__ out, int out_size, int base, int gw)
{
    const int lane = threadIdx.x & 31;
    const int s  = lane & 3;       // slice: owns h-cols j0..j0+7
    const int g8 = lane >> 2;      // group 0..7
    const int gb = lane & 28;
    const int j0 = s * 8;

    int   node[V];
    float hreg[V][8], w2r[V];
    float2 xc[V];

#pragma unroll
    for (int u = 0; u < V; u++) {
        node[u] = base + u * 8 + g8;
#pragma unroll
        for (int i = 0; i < 8; i++) hreg[u][i] = h0[node[u] * 32 + j0 + i];
        w2r[u] = W2[node[u]];
        xc[u]  = *(const float2*)(x + (size_t)node[u] * 8 + 2 * s);
    }
    float w1r[8];
#pragma unroll
    for (int i = 0; i < 8; i++) w1r[i] = sw->w1[j0 + i];

    ull bz[4], br[4], bh[4];
#pragma unroll
    for (int i = 0; i < 4; i++) {
        bz[i] = ((const ull*)&sw->cbz[j0])[i];
        br[i] = ((const ull*)&sw->cbr[j0])[i];
        bh[i] = ((const ull*)&sw->cbh[j0])[i];
    }

#pragma unroll 1
    for (int t = 0; t < T_STEPS; ++t) {
        // ---------- phase 1: z, r pre-activations ----------
        ull az[V][4], ar[V][4];
#pragma unroll
        for (int u = 0; u < V; u++)
#pragma unroll
            for (int i = 0; i < 4; i++) { az[u][i] = bz[i]; ar[u][i] = br[i]; }

        // h-part: sp rolled, c unrolled
#pragma unroll 1
        for (int sp = 0; sp < 4; sp++) {
#pragma unroll
            for (int c = 0; c < 8; c++) {
                const int k = 8 + sp * 8 + c;
                const ulonglong2 wz0 = *(const ulonglong2*)&sw->z[k * 32 + j0];
                const ulonglong2 wz1 = *(const ulonglong2*)&sw->z[k * 32 + j0 + 4];
                const ulonglong2 wr0 = *(const ulonglong2*)&sw->r[k * 32 + j0];
                const ulonglong2 wr1 = *(const ulonglong2*)&sw->r[k * 32 + j0 + 4];
#pragma unroll
                for (int u = 0; u < V; u++) {
                    ull m = pack2(__shfl_sync(0xffffffffu, hreg[u][c], gb + sp));
                    fma2(az[u][0], m, wz0.x); fma2(az[u][1], m, wz0.y);
                    fma2(az[u][2], m, wz1.x); fma2(az[u][3], m, wz1.y);
                    fma2(ar[u][0], m, wr0.x); fma2(ar[u][1], m, wr0.y);
                    fma2(ar[u][2], m, wr1.x); fma2(ar[u][3], m, wr1.y);
                }
            }
        }
        // x-part: row k = sp*2 + c2, owner lane gb+sp, register .x/.y
#pragma unroll
        for (int c2 = 0; c2 < 2; c2++) {
#pragma unroll
            for (int sp = 0; sp < 4; sp++) {
                const int k = sp * 2 + c2;
                const ulonglong2 wz0 = *(const ulonglong2*)&sw->z[k * 32 + j0];
                const ulonglong2 wz1 = *(const ulonglong2*)&sw->z[k * 32 + j0 + 4];
                const ulonglong2 wr0 = *(const ulonglong2*)&sw->r[k * 32 + j0];
                const ulonglong2 wr1 = *(const ulonglong2*)&sw->r[k * 32 + j0 + 4];
#pragma unroll
                for (int u = 0; u < V; u++) {
                    float xv = c2 ? xc[u].y : xc[u].x;
                    ull m = pack2(__shfl_sync(0xffffffffu, xv, gb + sp));
                    fma2(az[u][0], m, wz0.x); fma2(az[u][1], m, wz0.y);
                    fma2(az[u][2], m, wz1.x); fma2(az[u][3], m, wz1.y);
                    fma2(ar[u][0], m, wr0.x); fma2(ar[u][1], m, wr0.y);
                    fma2(ar[u][2], m, wr1.x); fma2(ar[u][3], m, wr1.y);
                }
            }
        }

        // ---------- gg = h * sigmoid(r)  (ar dies here) ----------
        float gg[V][8];
#pragma unroll
        for (int u = 0; u < V; u++)
#pragma unroll
            for (int i = 0; i < 4; i++) {
                float a, b;
                unpack2(ar[u][i], a, b);
                gg[u][2*i]   = hreg[u][2*i]   * sigm(a);
                gg[u][2*i+1] = hreg[u][2*i+1] * sigm(b);
            }

        // ---------- phase 2: candidate ----------
        ull ah[V][4];
#pragma unroll
        for (int u = 0; u < V; u++)
#pragma unroll
            for (int i = 0; i < 4; i++) ah[u][i] = bh[i];

        // x-part (xc consumed here)
#pragma unroll
        for (int c2 = 0; c2 < 2; c2++) {
#pragma unroll
            for (int sp = 0; sp < 4; sp++) {
                const int k = sp * 2 + c2;
                const ulonglong2 w0 = *(const ulonglong2*)&sw->h[k * 32 + j0];
                const ulonglong2 w1 = *(const ulonglong2*)&sw->h[k * 32 + j0 + 4];
#pragma unroll
                for (int u = 0; u < V; u++) {
                    float xv = c2 ? xc[u].y : xc[u].x;
                    ull m = pack2(__shfl_sync(0xffffffffu, xv, gb + sp));
                    fma2(ah[u][0], m, w0.x); fma2(ah[u][1], m, w0.y);
                    fma2(ah[u][2], m, w1.x); fma2(ah[u][3], m, w1.y);
                }
            }
        }

        // prefetch next x (xc now dead; ~3000 cyc of cover below)
        if (t + 1 < T_STEPS) {
            const float* xb = x + (size_t)(t + 1) * (N_NODES * 8);
#pragma unroll
            for (int u = 0; u < V; u++)
                xc[u] = *(const float2*)(xb + (size_t)node[u] * 8 + 2 * s);
        }

        // ---------- zz = sigmoid(az) (az dies; overlaps p2h below) ----------
        float zz[V][8];
#pragma unroll
        for (int u = 0; u < V; u++)
#pragma unroll
            for (int i = 0; i < 4; i++) {
                float a, b;
                unpack2(az[u][i], a, b);
                zz[u][2*i] = sigm(a); zz[u][2*i+1] = sigm(b);
            }

        // p2 h-part: ah += Whh . (h*r)
#pragma unroll 1
        for (int sp = 0; sp < 4; sp++) {
#pragma unroll
            for (int c = 0; c < 8; c++) {
                const int k = 8 + sp * 8 + c;
                const ulonglong2 w0 = *(const ulonglong2*)&sw->h[k * 32 + j0];
                const ulonglong2 w1 = *(const ulonglong2*)&sw->h[k * 32 + j0 + 4];
#pragma unroll
                for (int u = 0; u < V; u++) {
                    ull m = pack2(__shfl_sync(0xffffffffu, gg[u][c], gb + sp));
                    fma2(ah[u][0], m, w0.x); fma2(ah[u][1], m, w0.y);
                    fma2(ah[u][2], m, w1.x); fma2(ah[u][3], m, w1.y);
                }
            }
        }

        // ---------- update + fused readout ----------
        float st = 0.0f;
#pragma unroll
        for (int u = 0; u < V; u++) {
            float p = 0.0f;
#pragma unroll
            for (int i = 0; i < 4; i++) {
                float a, b;
                unpack2(ah[u][i], a, b);
                float t0 = tanha(a), t1 = tanha(b);
                float h0v = hreg[u][2*i], h1v = hreg[u][2*i+1];
                float hn0 = t0 + zz[u][2*i]   * (h0v - t0);
                float hn1 = t1 + zz[u][2*i+1] * (h1v - t1);
                hreg[u][2*i] = hn0; hreg[u][2*i+1] = hn1;
                p = fmaf(lrelu(hn0), w1r[2*i],   p);
                p = fmaf(lrelu(hn1), w1r[2*i+1], p);
            }
            p += __shfl_xor_sync(0xffffffffu, p, 1);
            p += __shfl_xor_sync(0xffffffffu, p, 2);
            st += lrelu(p + b1s) * w2r[u];
        }
        st += __shfl_xor_sync(0xffffffffu, st, 4);
        st += __shfl_xor_sync(0xffffffffu, st, 8);
        st += __shfl_xor_sync(0xffffffffu, st, 16);
        if (lane == 0) g_scratch[t * NW + gw] = st;
    }

    if (out_size >= N_NODES * 32) {
        const int hoff = out_size - N_NODES * 32;
#pragma unroll
        for (int u = 0; u < V; u++)
#pragma unroll
            for (int i = 0; i < 8; i++)
                out[hoff + node[u] * 32 + j0 + i] = hreg[u][i];
    }
}

__global__ void __launch_bounds__(128, 1)
gru_kernel(const float* __restrict__ x, const float* __restrict__ h0,
           const float* __restrict__ Wxz, const float* __restrict__ bxz,
           const float* __restrict__ Whz, const float* __restrict__ bhz,
           const float* __restrict__ Wxr, const float* __restrict__ bxr,
           const float* __restrict__ Whr, const float* __restrict__ bhr,
           const float* __restrict__ Wxh, const float* __restrict__ bxh,
           const float* __restrict__ Whh, const float* __restrict__ bhh,
           const float* __restrict__ W1,  const float* __restrict__ b1,
           const float* __restrict__ W2,
           float* __restrict__ out, int out_size)
{
    __shared__ __align__(16) SW sw;

    for (int i = threadIdx.x; i < 8 * 32; i += 128) {
        sw.z[i] = Wxz[i]; sw.r[i] = Wxr[i]; sw.h[i] = Wxh[i];
    }
    for (int i = threadIdx.x; i < 32 * 32; i += 128) {
        sw.z[256 + i] = Whz[i]; sw.r[256 + i] = Whr[i]; sw.h[256 + i] = Whh[i];
    }
    if (threadIdx.x < 32) {
        int i = threadIdx.x;
        sw.cbz[i] = bxz[i] + bhz[i];
        sw.cbr[i] = bxr[i] + bhr[i];
        sw.cbh[i] = bxh[i] + bhh[i];
        sw.w1[i]  = W1[i];
    }
    __syncthreads();

    const int gw = blockIdx.x * 4 + (threadIdx.x >> 5);
    const float b1s = b1[0];

    if (blockIdx.x < NB5) {
        gru_warp<5>(&sw, x, h0, W2, b1s, out, out_size, 40 * gw, gw);
    } else {
        gru_warp<4>(&sw, x, h0, W2, b1s, out, out_size,
                    5280 + 32 * (gw - 4 * NB5), gw);
    }
}

__global__ void reduce_out(const float* __restrict__ b2,
                           float* __restrict__ out, int out_size)
{
    const int t = blockIdx.x;
    float s = 0.0f;
    for (int w = threadIdx.x; w < NW; w += 256)
        s += g_scratch[t * NW + w];
#pragma unroll
    for (int o = 16; o; o >>= 1) s += __shfl_xor_sync(0xffffffffu, s, o);
    __shared__ float red[8];
    if ((threadIdx.x & 31) == 0) red[threadIdx.x >> 5] = s;
    __syncthreads();
    if (threadIdx.x < 8) {
        s = red[threadIdx.x];
#pragma unroll
        for (int o = 4; o; o >>= 1) s += __shfl_xor_sync(0x000000ffu, s, o);
        if (threadIdx.x == 0) {
            bool wr = (out_size >= T_STEPS + N_NODES * 32) || (out_size < N_NODES * 32);
            if (wr && t < out_size) out[t] = s + b2[0];
        }
    }
}

extern "C" void kernel_launch(void* const* d_in, const int* in_sizes, int n_in,
                              void* d_out, int out_size) {
    const float* x   = (const float*)d_in[0];
    const float* h0  = (const float*)d_in[3];
    const float* Wxz = (const float*)d_in[4];
    const float* bxz = (const float*)d_in[5];
    const float* Whz = (const float*)d_in[6];
    const float* bhz = (const float*)d_in[7];
    const float* Wxr = (const float*)d_in[8];
    const float* bxr = (const float*)d_in[9];
    const float* Whr = (const float*)d_in[10];
    const float* bhr = (const float*)d_in[11];
    const float* Wxh = (const float*)d_in[12];
    const float* bxh = (const float*)d_in[13];
    const float* Whh = (const float*)d_in[14];
    const float* bhh = (const float*)d_in[15];
    const float* W1  = (const float*)d_in[16];
    const float* b1  = (const float*)d_in[17];
    const float* W2  = (const float*)d_in[18];
    const float* b2  = (const float*)d_in[19];
    float* out = (float*)d_out;

    gru_kernel<<<148, 128>>>(x, h0, Wxz, bxz, Whz, bhz, Wxr, bxr, Whr, bhr,
                             Wxh, bxh, Whh, bhh, W1, b1, W2, out, out_size);
    reduce_out<<<T_STEPS, 256>>>(b2, out, out_size);
}